// round 13
// baseline (speedup 1.0000x reference)
#include <cuda_runtime.h>
#include <cuda_bf16.h>

// Gumbel-Sinkhorn, multiplicative form (R10 chassis + bf16 column sweeps).
//   E = exp((gamma + noise) * 5)            (once)
//   repeat niters: r_i = 1/sum_j E_ij c_j ;  c_j = 1/sum_i E_ij r_i
//   out_ij = E_ij * r_i * c_j
//
// One CTA (128 threads) per matrix, 2 CTAs/SM. l1tex-bound per R10 profile;
// the col sweep (512 of ~712 wf/iter) is the dominant traffic, so E is ALSO
// stored as bf16 (half the bytes) and all but the last 3 iterations run the
// column pass on the bf16 copy (bf16 = fp32 top half: reconstruct with one
// shift/mask, ALU pipe is idle). The last 3 iterations use the exact fp32
// sweep so bf16 perturbations are contracted away; row pass + epilogue are
// always exact fp32 (register rowE / fp32 Es).

#define NN 128
#define STRIDE 132           // fp32 Es row stride (floats)
#define HW 64                // bf16 Eh row stride in 32-bit words (= 256B rows)
#define TEMP_INV 5.0f

typedef unsigned long long ull;

__device__ __forceinline__ void fma2(ull& d, ull a, ull b) {
    asm("fma.rn.f32x2 %0, %1, %2, %0;" : "+l"(d) : "l"(a), "l"(b));
}
__device__ __forceinline__ ull add2(ull a, ull b) {
    ull r; asm("add.rn.f32x2 %0, %1, %2;" : "=l"(r) : "l"(a), "l"(b)); return r;
}
__device__ __forceinline__ ull splat2(float x) {
    ull r; asm("mov.b64 %0, {%1, %1};" : "=l"(r) : "f"(x)); return r;
}
__device__ __forceinline__ void unpack2(ull v, float& lo, float& hi) {
    asm("mov.b64 {%0, %1}, %2;" : "=f"(lo), "=f"(hi) : "l"(v));
}

__global__ __launch_bounds__(128) void sinkhorn_kernel(
    const float* __restrict__ gamma,
    const float* __restrict__ noise,
    const int*   __restrict__ niters_p,
    float*       __restrict__ out)
{
    extern __shared__ float smem[];
    float*    Es   = smem;                    // NN * STRIDE fp32
    float*    r_s  = smem + NN * STRIDE;      // NN
    float*    c_s  = r_s + NN;                // NN
    float*    part = c_s + NN;                // 4 * NN
    unsigned* Eh   = reinterpret_cast<unsigned*>(part + 4 * NN);  // NN*HW words (bf16x2)

    const int tid = threadIdx.x;
    const int w   = tid >> 5;
    const int l   = tid & 31;
    const int hw  = l >> 4;                   // half-warp (row parity)
    const int hl  = l & 15;                   // lane within half-warp
    const long long base = (long long)blockIdx.x * (NN * NN);
    const int niters = *niters_p;

    // ---- Prologue: E = exp((gamma + noise)*5) -> Es (fp32) + Eh (bf16) ----
    const float4* g4 = reinterpret_cast<const float4*>(gamma);
    const float4* n4 = reinterpret_cast<const float4*>(noise + base);
    #pragma unroll
    for (int k = 0; k < 32; ++k) {
        int v  = k * 128 + tid;           // float4 index 0..4095
        int i  = v >> 5;                  // row
        int j4 = (v & 31) * 4;            // col
        float4 g = g4[v];
        float4 u = n4[v];
        float4 e;
        e.x = __expf((g.x + u.x) * TEMP_INV);
        e.y = __expf((g.y + u.y) * TEMP_INV);
        e.z = __expf((g.z + u.z) * TEMP_INV);
        e.w = __expf((g.w + u.w) * TEMP_INV);
        *reinterpret_cast<float4*>(&Es[i * STRIDE + j4]) = e;
        __nv_bfloat162 h0 = __float22bfloat162_rn(make_float2(e.x, e.y));
        __nv_bfloat162 h1 = __float22bfloat162_rn(make_float2(e.z, e.w));
        uint2 hv;
        hv.x = *reinterpret_cast<unsigned*>(&h0);
        hv.y = *reinterpret_cast<unsigned*>(&h1);
        *reinterpret_cast<uint2*>(&Eh[i * HW + (j4 >> 1)]) = hv;
    }
    c_s[tid] = 1.0f;
    __syncthreads();

    // ---- Register row cache (packed pairs): thread t owns row t ----
    ull rowE[64];
    #pragma unroll
    for (int m = 0; m < 32; ++m) {
        ulonglong2 e = *reinterpret_cast<const ulonglong2*>(&Es[tid * STRIDE + 4 * m]);
        rowE[2 * m + 0] = e.x;
        rowE[2 * m + 1] = e.y;
    }

    // ---- Sinkhorn iterations ----
    for (int it = 0; it < niters; ++it) {
        // Row pass (always fp32): S_t = sum_j rowE[j] * c[j]
        ull a0 = 0, a1 = 0, a2 = 0, a3 = 0;
        #pragma unroll
        for (int m = 0; m < 16; ++m) {
            ulonglong2 c0 = *reinterpret_cast<const ulonglong2*>(&c_s[8 * m]);
            ulonglong2 c1 = *reinterpret_cast<const ulonglong2*>(&c_s[8 * m + 4]);
            fma2(a0, rowE[4 * m + 0], c0.x);
            fma2(a1, rowE[4 * m + 1], c0.y);
            fma2(a2, rowE[4 * m + 2], c1.x);
            fma2(a3, rowE[4 * m + 3], c1.y);
        }
        ull as = add2(add2(a0, a1), add2(a2, a3));
        float slo, shi; unpack2(as, slo, shi);
        r_s[tid] = __fdividef(1.0f, slo + shi);
        __syncwarp();   // warp w's col sweep only needs r_s[32w..32w+31]

        if (it < niters - 3) {
            // ---- bf16 col sweep: half-warp per row, 8 cols per lane ----
            float acc0 = 0.f, acc1 = 0.f, acc2 = 0.f, acc3 = 0.f;
            float acc4 = 0.f, acc5 = 0.f, acc6 = 0.f, acc7 = 0.f;
            #pragma unroll
            for (int g = 0; g < 16; ++g) {
                int i0 = 32 * w + 2 * g + hw;
                float ri = r_s[i0];
                uint4 h = *reinterpret_cast<const uint4*>(&Eh[i0 * HW + hl * 4]);
                acc0 = fmaf(__uint_as_float(h.x << 16),          ri, acc0);
                acc1 = fmaf(__uint_as_float(h.x & 0xFFFF0000u),  ri, acc1);
                acc2 = fmaf(__uint_as_float(h.y << 16),          ri, acc2);
                acc3 = fmaf(__uint_as_float(h.y & 0xFFFF0000u),  ri, acc3);
                acc4 = fmaf(__uint_as_float(h.z << 16),          ri, acc4);
                acc5 = fmaf(__uint_as_float(h.z & 0xFFFF0000u),  ri, acc5);
                acc6 = fmaf(__uint_as_float(h.w << 16),          ri, acc6);
                acc7 = fmaf(__uint_as_float(h.w & 0xFFFF0000u),  ri, acc7);
            }
            // combine the two half-warps (same columns, different rows)
            acc0 += __shfl_xor_sync(0xffffffffu, acc0, 16);
            acc1 += __shfl_xor_sync(0xffffffffu, acc1, 16);
            acc2 += __shfl_xor_sync(0xffffffffu, acc2, 16);
            acc3 += __shfl_xor_sync(0xffffffffu, acc3, 16);
            acc4 += __shfl_xor_sync(0xffffffffu, acc4, 16);
            acc5 += __shfl_xor_sync(0xffffffffu, acc5, 16);
            acc6 += __shfl_xor_sync(0xffffffffu, acc6, 16);
            acc7 += __shfl_xor_sync(0xffffffffu, acc7, 16);
            if (hw == 0) {
                float4 p0; p0.x = acc0; p0.y = acc1; p0.z = acc2; p0.w = acc3;
                float4 p1; p1.x = acc4; p1.y = acc5; p1.z = acc6; p1.w = acc7;
                *reinterpret_cast<float4*>(&part[w * NN + 8 * hl]) = p0;
                *reinterpret_cast<float4*>(&part[w * NN + 8 * hl + 4]) = p1;
            }
        } else {
            // ---- exact fp32 col sweep (last 3 iterations) ----
            ull b0 = 0, b1 = 0, b2 = 0, b3 = 0;
            #pragma unroll
            for (int g = 0; g < 8; ++g) {
                float4 rv = *reinterpret_cast<const float4*>(&r_s[32 * w + 4 * g]);
                ull rr0 = splat2(rv.x);
                ull rr1 = splat2(rv.y);
                ull rr2 = splat2(rv.z);
                ull rr3 = splat2(rv.w);
                int i0 = 32 * w + 4 * g;
                ulonglong2 e0 = *reinterpret_cast<const ulonglong2*>(&Es[(i0 + 0) * STRIDE + 4 * l]);
                fma2(b0, e0.x, rr0); fma2(b1, e0.y, rr0);
                ulonglong2 e1 = *reinterpret_cast<const ulonglong2*>(&Es[(i0 + 1) * STRIDE + 4 * l]);
                fma2(b2, e1.x, rr1); fma2(b3, e1.y, rr1);
                ulonglong2 e2 = *reinterpret_cast<const ulonglong2*>(&Es[(i0 + 2) * STRIDE + 4 * l]);
                fma2(b0, e2.x, rr2); fma2(b1, e2.y, rr2);
                ulonglong2 e3 = *reinterpret_cast<const ulonglong2*>(&Es[(i0 + 3) * STRIDE + 4 * l]);
                fma2(b2, e3.x, rr3); fma2(b3, e3.y, rr3);
            }
            ull p01 = add2(b0, b2);
            ull p23 = add2(b1, b3);
            ulonglong2 pv; pv.x = p01; pv.y = p23;
            *reinterpret_cast<ulonglong2*>(&part[w * NN + 4 * l]) = pv;
        }
        __syncthreads();

        // Cross-warp column reduce: thread t handles column t (conflict-free)
        float T = (part[0 * NN + tid] + part[1 * NN + tid])
                + (part[2 * NN + tid] + part[3 * NN + tid]);
        c_s[tid] = __fdividef(1.0f, T);
        __syncthreads();
    }

    // ---- Epilogue: out = E * r * c, coalesced float4 (fp32 Es) ----
    float4* o4 = reinterpret_cast<float4*>(out + base);
    #pragma unroll
    for (int k = 0; k < 32; ++k) {
        int v  = k * 128 + tid;
        int i  = v >> 5;
        int j4 = (v & 31) * 4;
        float ri = r_s[i];
        float4 e = *reinterpret_cast<const float4*>(&Es[i * STRIDE + j4]);
        float4 o;
        o.x = e.x * ri * c_s[j4 + 0];
        o.y = e.y * ri * c_s[j4 + 1];
        o.z = e.z * ri * c_s[j4 + 2];
        o.w = e.w * ri * c_s[j4 + 3];
        o4[v] = o;
    }
}

extern "C" void kernel_launch(void* const* d_in, const int* in_sizes, int n_in,
                              void* d_out, int out_size)
{
    // Identify inputs by element count:
    //   gamma: 128*128, noise: B*128*128 (largest), niters: 1
    int gi = -1, ni = -1, si = -1;
    long long best = -1;
    for (int k = 0; k < n_in; ++k) {
        if (in_sizes[k] == 1) { si = k; }
        else if (in_sizes[k] == NN * NN && gi < 0) { gi = k; }
        if ((long long)in_sizes[k] > best) { best = in_sizes[k]; ni = k; }
    }
    if (ni == gi) {
        for (int k = 0; k < n_in; ++k)
            if (k != gi && in_sizes[k] == NN * NN) { ni = k; break; }
    }

    const float* gamma = (const float*)d_in[gi];
    const float* noise = (const float*)d_in[ni];
    const int*   nit   = (const int*)d_in[si];
    float* out = (float*)d_out;

    int B = in_sizes[ni] / (NN * NN);

    const int smem_bytes =
        (NN * STRIDE + 2 * NN + 4 * NN) * (int)sizeof(float)   // Es + vectors + part
        + NN * HW * (int)sizeof(unsigned);                      // Eh (bf16x2 words)
    static bool attr_set = false;
    if (!attr_set) {
        cudaFuncSetAttribute(sinkhorn_kernel,
                             cudaFuncAttributeMaxDynamicSharedMemorySize,
                             smem_bytes);
        attr_set = true;
    }

    sinkhorn_kernel<<<B, 128, smem_bytes>>>(gamma, noise, nit, out);
}

// round 14
// speedup vs baseline: 1.5727x; 1.5727x over previous
#include <cuda_runtime.h>
#include <cuda_bf16.h>

// Gumbel-Sinkhorn, multiplicative form (R10 chassis + bf16 column sweeps).
//   E = exp((gamma + noise) * 5)            (once)
//   repeat niters: r_i = 1/sum_j E_ij c_j ;  c_j = 1/sum_i E_ij r_i
//   out_ij = E_ij * r_i * c_j
//
// One CTA (128 threads) per matrix, 2 CTAs/SM. l1tex-bound per R10 profile;
// the col sweep (512 of ~712 wf/iter) is the dominant traffic, so E is ALSO
// stored as bf16 (half the bytes) and all but the last 3 iterations run the
// column pass on the bf16 copy (bf16 = fp32 top half: reconstruct with one
// shift/mask, ALU pipe is idle). The last 3 iterations use the exact fp32
// sweep so bf16 perturbations are contracted away; row pass + epilogue are
// always exact fp32 (register rowE / fp32 Es).

#define NN 128
#define STRIDE 132           // fp32 Es row stride (floats)
#define HW 64                // bf16 Eh row stride in 32-bit words (= 256B rows)
#define TEMP_INV 5.0f

typedef unsigned long long ull;

__device__ __forceinline__ void fma2(ull& d, ull a, ull b) {
    asm("fma.rn.f32x2 %0, %1, %2, %0;" : "+l"(d) : "l"(a), "l"(b));
}
__device__ __forceinline__ ull add2(ull a, ull b) {
    ull r; asm("add.rn.f32x2 %0, %1, %2;" : "=l"(r) : "l"(a), "l"(b)); return r;
}
__device__ __forceinline__ ull splat2(float x) {
    ull r; asm("mov.b64 %0, {%1, %1};" : "=l"(r) : "f"(x)); return r;
}
__device__ __forceinline__ void unpack2(ull v, float& lo, float& hi) {
    asm("mov.b64 {%0, %1}, %2;" : "=f"(lo), "=f"(hi) : "l"(v));
}

__global__ __launch_bounds__(128) void sinkhorn_kernel(
    const float* __restrict__ gamma,
    const float* __restrict__ noise,
    const int*   __restrict__ niters_p,
    float*       __restrict__ out)
{
    extern __shared__ float smem[];
    float*    Es   = smem;                    // NN * STRIDE fp32
    float*    r_s  = smem + NN * STRIDE;      // NN
    float*    c_s  = r_s + NN;                // NN
    float*    part = c_s + NN;                // 4 * NN
    unsigned* Eh   = reinterpret_cast<unsigned*>(part + 4 * NN);  // NN*HW words (bf16x2)

    const int tid = threadIdx.x;
    const int w   = tid >> 5;
    const int l   = tid & 31;
    const int hw  = l >> 4;                   // half-warp (row parity)
    const int hl  = l & 15;                   // lane within half-warp
    const long long base = (long long)blockIdx.x * (NN * NN);
    const int niters = *niters_p;

    // ---- Prologue: E = exp((gamma + noise)*5) -> Es (fp32) + Eh (bf16) ----
    const float4* g4 = reinterpret_cast<const float4*>(gamma);
    const float4* n4 = reinterpret_cast<const float4*>(noise + base);
    #pragma unroll
    for (int k = 0; k < 32; ++k) {
        int v  = k * 128 + tid;           // float4 index 0..4095
        int i  = v >> 5;                  // row
        int j4 = (v & 31) * 4;            // col
        float4 g = g4[v];
        float4 u = n4[v];
        float4 e;
        e.x = __expf((g.x + u.x) * TEMP_INV);
        e.y = __expf((g.y + u.y) * TEMP_INV);
        e.z = __expf((g.z + u.z) * TEMP_INV);
        e.w = __expf((g.w + u.w) * TEMP_INV);
        *reinterpret_cast<float4*>(&Es[i * STRIDE + j4]) = e;
        __nv_bfloat162 h0 = __float22bfloat162_rn(make_float2(e.x, e.y));
        __nv_bfloat162 h1 = __float22bfloat162_rn(make_float2(e.z, e.w));
        uint2 hv;
        hv.x = *reinterpret_cast<unsigned*>(&h0);
        hv.y = *reinterpret_cast<unsigned*>(&h1);
        *reinterpret_cast<uint2*>(&Eh[i * HW + (j4 >> 1)]) = hv;
    }
    c_s[tid] = 1.0f;
    __syncthreads();

    // ---- Register row cache (packed pairs): thread t owns row t ----
    ull rowE[64];
    #pragma unroll
    for (int m = 0; m < 32; ++m) {
        ulonglong2 e = *reinterpret_cast<const ulonglong2*>(&Es[tid * STRIDE + 4 * m]);
        rowE[2 * m + 0] = e.x;
        rowE[2 * m + 1] = e.y;
    }

    // ---- Sinkhorn iterations ----
    for (int it = 0; it < niters; ++it) {
        // Row pass (always fp32): S_t = sum_j rowE[j] * c[j]
        ull a0 = 0, a1 = 0, a2 = 0, a3 = 0;
        #pragma unroll
        for (int m = 0; m < 16; ++m) {
            ulonglong2 c0 = *reinterpret_cast<const ulonglong2*>(&c_s[8 * m]);
            ulonglong2 c1 = *reinterpret_cast<const ulonglong2*>(&c_s[8 * m + 4]);
            fma2(a0, rowE[4 * m + 0], c0.x);
            fma2(a1, rowE[4 * m + 1], c0.y);
            fma2(a2, rowE[4 * m + 2], c1.x);
            fma2(a3, rowE[4 * m + 3], c1.y);
        }
        ull as = add2(add2(a0, a1), add2(a2, a3));
        float slo, shi; unpack2(as, slo, shi);
        r_s[tid] = __fdividef(1.0f, slo + shi);
        __syncwarp();   // warp w's col sweep only needs r_s[32w..32w+31]

        if (it < niters - 3) {
            // ---- bf16 col sweep: half-warp per row, 8 cols per lane ----
            float acc0 = 0.f, acc1 = 0.f, acc2 = 0.f, acc3 = 0.f;
            float acc4 = 0.f, acc5 = 0.f, acc6 = 0.f, acc7 = 0.f;
            #pragma unroll
            for (int g = 0; g < 16; ++g) {
                int i0 = 32 * w + 2 * g + hw;
                float ri = r_s[i0];
                uint4 h = *reinterpret_cast<const uint4*>(&Eh[i0 * HW + hl * 4]);
                acc0 = fmaf(__uint_as_float(h.x << 16),          ri, acc0);
                acc1 = fmaf(__uint_as_float(h.x & 0xFFFF0000u),  ri, acc1);
                acc2 = fmaf(__uint_as_float(h.y << 16),          ri, acc2);
                acc3 = fmaf(__uint_as_float(h.y & 0xFFFF0000u),  ri, acc3);
                acc4 = fmaf(__uint_as_float(h.z << 16),          ri, acc4);
                acc5 = fmaf(__uint_as_float(h.z & 0xFFFF0000u),  ri, acc5);
                acc6 = fmaf(__uint_as_float(h.w << 16),          ri, acc6);
                acc7 = fmaf(__uint_as_float(h.w & 0xFFFF0000u),  ri, acc7);
            }
            // combine the two half-warps (same columns, different rows)
            acc0 += __shfl_xor_sync(0xffffffffu, acc0, 16);
            acc1 += __shfl_xor_sync(0xffffffffu, acc1, 16);
            acc2 += __shfl_xor_sync(0xffffffffu, acc2, 16);
            acc3 += __shfl_xor_sync(0xffffffffu, acc3, 16);
            acc4 += __shfl_xor_sync(0xffffffffu, acc4, 16);
            acc5 += __shfl_xor_sync(0xffffffffu, acc5, 16);
            acc6 += __shfl_xor_sync(0xffffffffu, acc6, 16);
            acc7 += __shfl_xor_sync(0xffffffffu, acc7, 16);
            if (hw == 0) {
                float4 p0; p0.x = acc0; p0.y = acc1; p0.z = acc2; p0.w = acc3;
                float4 p1; p1.x = acc4; p1.y = acc5; p1.z = acc6; p1.w = acc7;
                *reinterpret_cast<float4*>(&part[w * NN + 8 * hl]) = p0;
                *reinterpret_cast<float4*>(&part[w * NN + 8 * hl + 4]) = p1;
            }
        } else {
            // ---- exact fp32 col sweep (last 3 iterations) ----
            ull b0 = 0, b1 = 0, b2 = 0, b3 = 0;
            #pragma unroll
            for (int g = 0; g < 8; ++g) {
                float4 rv = *reinterpret_cast<const float4*>(&r_s[32 * w + 4 * g]);
                ull rr0 = splat2(rv.x);
                ull rr1 = splat2(rv.y);
                ull rr2 = splat2(rv.z);
                ull rr3 = splat2(rv.w);
                int i0 = 32 * w + 4 * g;
                ulonglong2 e0 = *reinterpret_cast<const ulonglong2*>(&Es[(i0 + 0) * STRIDE + 4 * l]);
                fma2(b0, e0.x, rr0); fma2(b1, e0.y, rr0);
                ulonglong2 e1 = *reinterpret_cast<const ulonglong2*>(&Es[(i0 + 1) * STRIDE + 4 * l]);
                fma2(b2, e1.x, rr1); fma2(b3, e1.y, rr1);
                ulonglong2 e2 = *reinterpret_cast<const ulonglong2*>(&Es[(i0 + 2) * STRIDE + 4 * l]);
                fma2(b0, e2.x, rr2); fma2(b1, e2.y, rr2);
                ulonglong2 e3 = *reinterpret_cast<const ulonglong2*>(&Es[(i0 + 3) * STRIDE + 4 * l]);
                fma2(b2, e3.x, rr3); fma2(b3, e3.y, rr3);
            }
            ull p01 = add2(b0, b2);
            ull p23 = add2(b1, b3);
            ulonglong2 pv; pv.x = p01; pv.y = p23;
            *reinterpret_cast<ulonglong2*>(&part[w * NN + 4 * l]) = pv;
        }
        __syncthreads();

        // Cross-warp column reduce: thread t handles column t (conflict-free)
        float T = (part[0 * NN + tid] + part[1 * NN + tid])
                + (part[2 * NN + tid] + part[3 * NN + tid]);
        c_s[tid] = __fdividef(1.0f, T);
        __syncthreads();
    }

    // ---- Epilogue: out = E * r * c, coalesced float4 (fp32 Es) ----
    float4* o4 = reinterpret_cast<float4*>(out + base);
    #pragma unroll
    for (int k = 0; k < 32; ++k) {
        int v  = k * 128 + tid;
        int i  = v >> 5;
        int j4 = (v & 31) * 4;
        float ri = r_s[i];
        float4 e = *reinterpret_cast<const float4*>(&Es[i * STRIDE + j4]);
        float4 o;
        o.x = e.x * ri * c_s[j4 + 0];
        o.y = e.y * ri * c_s[j4 + 1];
        o.z = e.z * ri * c_s[j4 + 2];
        o.w = e.w * ri * c_s[j4 + 3];
        o4[v] = o;
    }
}

extern "C" void kernel_launch(void* const* d_in, const int* in_sizes, int n_in,
                              void* d_out, int out_size)
{
    // Identify inputs by element count:
    //   gamma: 128*128, noise: B*128*128 (largest), niters: 1
    int gi = -1, ni = -1, si = -1;
    long long best = -1;
    for (int k = 0; k < n_in; ++k) {
        if (in_sizes[k] == 1) { si = k; }
        else if (in_sizes[k] == NN * NN && gi < 0) { gi = k; }
        if ((long long)in_sizes[k] > best) { best = in_sizes[k]; ni = k; }
    }
    if (ni == gi) {
        for (int k = 0; k < n_in; ++k)
            if (k != gi && in_sizes[k] == NN * NN) { ni = k; break; }
    }

    const float* gamma = (const float*)d_in[gi];
    const float* noise = (const float*)d_in[ni];
    const int*   nit   = (const int*)d_in[si];
    float* out = (float*)d_out;

    int B = in_sizes[ni] / (NN * NN);

    const int smem_bytes =
        (NN * STRIDE + 2 * NN + 4 * NN) * (int)sizeof(float)   // Es + vectors + part
        + NN * HW * (int)sizeof(unsigned);                      // Eh (bf16x2 words)
    static bool attr_set = false;
    if (!attr_set) {
        cudaFuncSetAttribute(sinkhorn_kernel,
                             cudaFuncAttributeMaxDynamicSharedMemorySize,
                             smem_bytes);
        attr_set = true;
    }

    sinkhorn_kernel<<<B, 128, smem_bytes>>>(gamma, noise, nit, out);
}

// round 15
// speedup vs baseline: 1.8367x; 1.1679x over previous
#include <cuda_runtime.h>

// Gumbel-Sinkhorn, multiplicative form (R10 chassis, instruction diet).
//   E = exp((gamma + noise) * 5)            (once)
//   repeat niters: r_i = 1/sum_j E_ij c_j ;  c_j = 1/sum_i E_ij r_i
//   out_ij = E_ij * r_i * c_j
//
// One CTA (128 threads) per matrix, 2 CTAs/SM. Regime (R3/R9/R10/R14
// evidence): at 2 CTAs/SM, per-SMSP issue-latency and smem wavefronts are
// both ~binding; time tracks instruction count while wf <= ~2000/iter.
// This round removes instructions without touching traffic:
//  - r stored DUPLICATED (r,r) by the row pass (one STS.64), so the col
//    pass loads ready-made (r_i,r_i) FFMA2 operands -> no splat movs.
//  - rcp.approx.f32 for both normalizations (no divide refinement).
//  - everything else identical to the 315us R10 kernel.

#define NN 128
#define STRIDE 132           // float4-aligned rows; column accesses conflict-free
#define TEMP_INV 5.0f

typedef unsigned long long ull;

__device__ __forceinline__ void fma2(ull& d, ull a, ull b) {
    asm("fma.rn.f32x2 %0, %1, %2, %0;" : "+l"(d) : "l"(a), "l"(b));
}
__device__ __forceinline__ ull add2(ull a, ull b) {
    ull r; asm("add.rn.f32x2 %0, %1, %2;" : "=l"(r) : "l"(a), "l"(b)); return r;
}
__device__ __forceinline__ void unpack2(ull v, float& lo, float& hi) {
    asm("mov.b64 {%0, %1}, %2;" : "=f"(lo), "=f"(hi) : "l"(v));
}
__device__ __forceinline__ float frcp(float x) {
    float r; asm("rcp.approx.f32 %0, %1;" : "=f"(r) : "f"(x)); return r;
}

__global__ __launch_bounds__(128) void sinkhorn_kernel(
    const float* __restrict__ gamma,
    const float* __restrict__ noise,
    const int*   __restrict__ niters_p,
    float*       __restrict__ out)
{
    extern __shared__ float smem[];
    float* Es   = smem;                    // NN * STRIDE
    float* r2   = smem + NN * STRIDE;      // 2*NN  (r duplicated: r2[2i]=r2[2i+1]=r_i)
    float* c_s  = r2 + 2 * NN;             // NN
    float* part = c_s + NN;                // 4 * NN  cross-warp column partials

    const int tid = threadIdx.x;
    const int w   = tid >> 5;
    const int l   = tid & 31;
    const long long base = (long long)blockIdx.x * (NN * NN);
    const int niters = *niters_p;

    // ---- Prologue: E = exp((gamma + noise) * 5), coalesced float4 ----
    const float4* g4 = reinterpret_cast<const float4*>(gamma);
    const float4* n4 = reinterpret_cast<const float4*>(noise + base);
    #pragma unroll
    for (int k = 0; k < 32; ++k) {
        int v  = k * 128 + tid;           // float4 index 0..4095
        int i  = v >> 5;                  // row
        int j4 = (v & 31) * 4;            // col
        float4 g = g4[v];
        float4 u = n4[v];
        float4 e;
        e.x = __expf((g.x + u.x) * TEMP_INV);
        e.y = __expf((g.y + u.y) * TEMP_INV);
        e.z = __expf((g.z + u.z) * TEMP_INV);
        e.w = __expf((g.w + u.w) * TEMP_INV);
        *reinterpret_cast<float4*>(&Es[i * STRIDE + j4]) = e;
    }
    c_s[tid] = 1.0f;
    __syncthreads();

    // ---- Register row cache (packed pairs): thread t owns row t ----
    ull rowE[64];
    #pragma unroll
    for (int m = 0; m < 32; ++m) {
        ulonglong2 e = *reinterpret_cast<const ulonglong2*>(&Es[tid * STRIDE + 4 * m]);
        rowE[2 * m + 0] = e.x;
        rowE[2 * m + 1] = e.y;
    }

    // ---- Sinkhorn iterations ----
    for (int it = 0; it < niters; ++it) {
        // Row pass: S_t = sum_j rowE[j] * c[j]; 4 packed accumulators.
        ull a0 = 0, a1 = 0, a2 = 0, a3 = 0;
        #pragma unroll
        for (int m = 0; m < 16; ++m) {
            ulonglong2 c0 = *reinterpret_cast<const ulonglong2*>(&c_s[8 * m]);
            ulonglong2 c1 = *reinterpret_cast<const ulonglong2*>(&c_s[8 * m + 4]);
            fma2(a0, rowE[4 * m + 0], c0.x);
            fma2(a1, rowE[4 * m + 1], c0.y);
            fma2(a2, rowE[4 * m + 2], c1.x);
            fma2(a3, rowE[4 * m + 3], c1.y);
        }
        ull as = add2(add2(a0, a1), add2(a2, a3));
        float slo, shi; unpack2(as, slo, shi);
        float r = frcp(slo + shi);
        // duplicated store: col pass reads (r_i, r_i) directly as an FFMA2 operand
        *reinterpret_cast<float2*>(&r2[2 * tid]) = make_float2(r, r);
        __syncwarp();   // warp w's col sweep only needs rows 32w..32w+31,
                        // written by this same warp — no CTA barrier.

        // Col pass: warp w sweeps rows 32w..32w+31, LDS.128 row loads
        // (as ulonglong2); r operands pre-splatted in smem.
        ull b0 = 0, b1 = 0, b2 = 0, b3 = 0;
        #pragma unroll
        for (int g = 0; g < 8; ++g) {
            int i0 = 32 * w + 4 * g;
            ulonglong2 rr01 = *reinterpret_cast<const ulonglong2*>(&r2[2 * i0]);
            ulonglong2 rr23 = *reinterpret_cast<const ulonglong2*>(&r2[2 * i0 + 4]);
            ulonglong2 e0 = *reinterpret_cast<const ulonglong2*>(&Es[(i0 + 0) * STRIDE + 4 * l]);
            fma2(b0, e0.x, rr01.x); fma2(b1, e0.y, rr01.x);
            ulonglong2 e1 = *reinterpret_cast<const ulonglong2*>(&Es[(i0 + 1) * STRIDE + 4 * l]);
            fma2(b2, e1.x, rr01.y); fma2(b3, e1.y, rr01.y);
            ulonglong2 e2 = *reinterpret_cast<const ulonglong2*>(&Es[(i0 + 2) * STRIDE + 4 * l]);
            fma2(b0, e2.x, rr23.x); fma2(b1, e2.y, rr23.x);
            ulonglong2 e3 = *reinterpret_cast<const ulonglong2*>(&Es[(i0 + 3) * STRIDE + 4 * l]);
            fma2(b2, e3.x, rr23.y); fma2(b3, e3.y, rr23.y);
        }
        ull p01 = add2(b0, b2);            // cols 4l, 4l+1
        ull p23 = add2(b1, b3);            // cols 4l+2, 4l+3
        ulonglong2 pv; pv.x = p01; pv.y = p23;
        *reinterpret_cast<ulonglong2*>(&part[w * NN + 4 * l]) = pv;
        __syncthreads();

        // Cross-warp column reduce: thread t handles column t (conflict-free)
        float T = (part[0 * NN + tid] + part[1 * NN + tid])
                + (part[2 * NN + tid] + part[3 * NN + tid]);
        c_s[tid] = frcp(T);
        __syncthreads();
    }

    // ---- Epilogue: out = E * r * c, coalesced float4 ----
    float4* o4 = reinterpret_cast<float4*>(out + base);
    #pragma unroll
    for (int k = 0; k < 32; ++k) {
        int v  = k * 128 + tid;
        int i  = v >> 5;
        int j4 = (v & 31) * 4;
        float ri = r2[2 * i];
        float4 e = *reinterpret_cast<const float4*>(&Es[i * STRIDE + j4]);
        float4 o;
        o.x = e.x * ri * c_s[j4 + 0];
        o.y = e.y * ri * c_s[j4 + 1];
        o.z = e.z * ri * c_s[j4 + 2];
        o.w = e.w * ri * c_s[j4 + 3];
        o4[v] = o;
    }
}

extern "C" void kernel_launch(void* const* d_in, const int* in_sizes, int n_in,
                              void* d_out, int out_size)
{
    // Identify inputs by element count:
    //   gamma: 128*128, noise: B*128*128 (largest), niters: 1
    int gi = -1, ni = -1, si = -1;
    long long best = -1;
    for (int k = 0; k < n_in; ++k) {
        if (in_sizes[k] == 1) { si = k; }
        else if (in_sizes[k] == NN * NN && gi < 0) { gi = k; }
        if ((long long)in_sizes[k] > best) { best = in_sizes[k]; ni = k; }
    }
    if (ni == gi) {
        for (int k = 0; k < n_in; ++k)
            if (k != gi && in_sizes[k] == NN * NN) { ni = k; break; }
    }

    const float* gamma = (const float*)d_in[gi];
    const float* noise = (const float*)d_in[ni];
    const int*   nit   = (const int*)d_in[si];
    float* out = (float*)d_out;

    int B = in_sizes[ni] / (NN * NN);

    const int smem_bytes = (NN * STRIDE + 3 * NN + 4 * NN) * (int)sizeof(float);
    static bool attr_set = false;
    if (!attr_set) {
        cudaFuncSetAttribute(sinkhorn_kernel,
                             cudaFuncAttributeMaxDynamicSharedMemorySize,
                             smem_bytes);
        attr_set = true;
    }

    sinkhorn_kernel<<<B, 128, smem_bytes>>>(gamma, noise, nit, out);
}